// round 1
// baseline (speedup 1.0000x reference)
#include <cuda_runtime.h>

// Problem constants
#define NN 50000
#define NE 600000

// Scratch layout (floats) in one device-global arena
#define OFF_RS_OUT 0
#define OFF_RS_IN  50000
#define OFF_T1     100000            // 50000*64
#define OFF_AGG1   3300000           // 50000*64
#define OFF_T2     6500000           // 50000*32
#define OFF_AGG2   8100000           // 50000*32
#define OFF_T3     9700000           // 50000*32
#define OFF_AGG3   11300000          // 50000*32
#define SCRATCH_TOTAL 12900000       // 51.6 MB

__device__ __align__(16) float g_scratch[SCRATCH_TOTAL];

// ---------------------------------------------------------------------------
// Zero the arena (degrees + agg buffers must be 0 at start of every replay)
// ---------------------------------------------------------------------------
__global__ void zero_kernel() {
    int i = blockIdx.x * blockDim.x + threadIdx.x;
    int n4 = SCRATCH_TOTAL / 4;
    if (i < n4) ((float4*)g_scratch)[i] = make_float4(0.f, 0.f, 0.f, 0.f);
}

// ---------------------------------------------------------------------------
// Degree histograms (float atomics; contention avg ~12 per node)
// ---------------------------------------------------------------------------
__global__ void degree_kernel(const int* __restrict__ src, const int* __restrict__ dst) {
    int i = blockIdx.x * blockDim.x + threadIdx.x;
    if (i >= NE) return;
    atomicAdd(&g_scratch[OFF_RS_OUT + __ldg(&src[i])], 1.0f);
    atomicAdd(&g_scratch[OFF_RS_IN  + __ldg(&dst[i])], 1.0f);
}

// deg -> rsqrt(max(deg,1)) in place, both arrays contiguous
__global__ void rsqrt_kernel() {
    int i = blockIdx.x * blockDim.x + threadIdx.x;
    if (i >= 2 * NN) return;
    g_scratch[i] = rsqrtf(fmaxf(g_scratch[i], 1.0f));
}

// ---------------------------------------------------------------------------
// Dense GEMM: out[n, 0..J) = f_out( f_in(X[n, 0..K)) @ W )
//   MODE_IN : 0 raw, 1 relu(v*rs_in[n] + bin[k]), 2 v*rs_in[n]
//   MODE_OUT: 0 raw, 1 *rs_out[n],               2 +bout[j]
// W resident in smem; X tile staged in smem with the input transform fused.
// ---------------------------------------------------------------------------
template<int K, int J, int MODE_IN, int MODE_OUT>
__global__ void __launch_bounds__(256) gemm_kernel(
    const float* __restrict__ X, const float* __restrict__ W,
    const float* __restrict__ rs_in, const float* __restrict__ bin,
    const float* __restrict__ rs_out, const float* __restrict__ bout,
    float* __restrict__ out)
{
    constexpr int JV = J / 4;          // float4 lanes across J
    constexpr int NB = 256 / JV;       // nodes per block-iteration
    constexpr int XS = K + 4;          // padded smem row stride (bank spread)

    __shared__ float sW[K * J];
    __shared__ float sX[NB * XS];
    __shared__ float sRS[NB];

    // Load W once (float4)
    for (int i = threadIdx.x; i < K * J / 4; i += 256)
        ((float4*)sW)[i] = __ldg(&((const float4*)W)[i]);

    const int node_local = threadIdx.x / JV;
    const int jv = threadIdx.x % JV;

    for (int base = blockIdx.x * NB; base < NN; base += gridDim.x * NB) {
        __syncthreads();
        // Stage X tile with fused input transform
        for (int i = threadIdx.x; i < NB * (K / 4); i += 256) {
            int nl = i / (K / 4);
            int kc = i % (K / 4);
            int n = base + nl;
            float4 v = make_float4(0.f, 0.f, 0.f, 0.f);
            if (n < NN) {
                v = __ldg((const float4*)&X[(size_t)n * K + 4 * kc]);
                if (MODE_IN == 1) {
                    float r = __ldg(&rs_in[n]);
                    float4 b = __ldg((const float4*)&bin[4 * kc]);
                    v.x = fmaxf(fmaf(v.x, r, b.x), 0.f);
                    v.y = fmaxf(fmaf(v.y, r, b.y), 0.f);
                    v.z = fmaxf(fmaf(v.z, r, b.z), 0.f);
                    v.w = fmaxf(fmaf(v.w, r, b.w), 0.f);
                } else if (MODE_IN == 2) {
                    float r = __ldg(&rs_in[n]);
                    v.x *= r; v.y *= r; v.z *= r; v.w *= r;
                }
            }
            *(float4*)&sX[nl * XS + 4 * kc] = v;
        }
        if (MODE_OUT == 1 && threadIdx.x < NB) {
            int n = base + threadIdx.x;
            sRS[threadIdx.x] = (n < NN) ? __ldg(&rs_out[n]) : 0.f;
        }
        __syncthreads();

        int n = base + node_local;
        if (n < NN) {
            float4 acc = make_float4(0.f, 0.f, 0.f, 0.f);
            if (MODE_OUT == 2) acc = __ldg((const float4*)&bout[4 * jv]);
            const float* xs = &sX[node_local * XS];
            #pragma unroll 8
            for (int k = 0; k < K; k++) {
                float xk = xs[k];
                float4 w = *(const float4*)&sW[k * J + 4 * jv];
                acc.x = fmaf(xk, w.x, acc.x);
                acc.y = fmaf(xk, w.y, acc.y);
                acc.z = fmaf(xk, w.z, acc.z);
                acc.w = fmaf(xk, w.w, acc.w);
            }
            if (MODE_OUT == 1) {
                float r = sRS[node_local];
                acc.x *= r; acc.y *= r; acc.z *= r; acc.w *= r;
            }
            *(float4*)&out[(size_t)n * J + 4 * jv] = acc;
        }
    }
}

// ---------------------------------------------------------------------------
// SpMM scatter-add: agg[dst[e], :] += tin[src[e], :], vectorized float4,
// one thread per (edge, float4-chunk), vector red to cut atomic op count 4x.
// ---------------------------------------------------------------------------
template<int F>
__global__ void spmm_kernel(const int* __restrict__ src, const int* __restrict__ dst,
                            const float* __restrict__ tin, float* __restrict__ agg)
{
    constexpr int C = F / 4;
    int i = blockIdx.x * blockDim.x + threadIdx.x;
    if (i >= NE * C) return;
    int e = i / C;
    int c = i % C;
    int s = __ldg(&src[e]);
    int d = __ldg(&dst[e]);
    float4 v = __ldg((const float4*)(tin + (size_t)s * F + 4 * c));
    float* p = agg + (size_t)d * F + 4 * c;
    asm volatile("red.global.add.v4.f32 [%0], {%1, %2, %3, %4};"
                 :: "l"(p), "f"(v.x), "f"(v.y), "f"(v.z), "f"(v.w)
                 : "memory");
}

// ---------------------------------------------------------------------------
// Epilogue of layer 2: z = agg2*rs_in + b2 (written to output) and
// t3 = z * rs_out (input to layer-3 aggregation) in one pass.
// ---------------------------------------------------------------------------
__global__ void epilogue_kernel(const float* __restrict__ b2, float* __restrict__ z_out) {
    int i = blockIdx.x * blockDim.x + threadIdx.x;   // over NN*8 float4s
    if (i >= NN * 8) return;
    int n = i >> 3;
    int kc = i & 7;
    float rin  = g_scratch[OFF_RS_IN + n];
    float rout = g_scratch[OFF_RS_OUT + n];
    float4 a = *(const float4*)&g_scratch[OFF_AGG2 + (size_t)n * 32 + 4 * kc];
    float4 b = __ldg((const float4*)&b2[4 * kc]);
    float4 z;
    z.x = fmaf(a.x, rin, b.x);
    z.y = fmaf(a.y, rin, b.y);
    z.z = fmaf(a.z, rin, b.z);
    z.w = fmaf(a.w, rin, b.w);
    *(float4*)&z_out[(size_t)n * 32 + 4 * kc] = z;
    float4 t;
    t.x = z.x * rout; t.y = z.y * rout; t.z = z.z * rout; t.w = z.w * rout;
    *(float4*)&g_scratch[OFF_T3 + (size_t)n * 32 + 4 * kc] = t;
}

// ---------------------------------------------------------------------------
extern "C" void kernel_launch(void* const* d_in, const int* in_sizes, int n_in,
                              void* d_out, int out_size)
{
    const float* features = (const float*)d_in[0];
    const int*   src      = (const int*)d_in[1];
    const int*   dst      = (const int*)d_in[2];
    const float* W1       = (const float*)d_in[3];
    const float* b1       = (const float*)d_in[4];
    const float* W2       = (const float*)d_in[5];
    const float* b2       = (const float*)d_in[6];
    const float* W3       = (const float*)d_in[7];
    const float* b3       = (const float*)d_in[8];

    float* z_out  = (float*)d_out;                 // [50000, 32]
    float* recon  = (float*)d_out + (size_t)NN * 32; // [50000, 128]

    float* sp = nullptr;
    cudaGetSymbolAddress((void**)&sp, g_scratch);
    float* rs_out = sp + OFF_RS_OUT;
    float* rs_in  = sp + OFF_RS_IN;
    float* t1     = sp + OFF_T1;
    float* agg1   = sp + OFF_AGG1;
    float* t2     = sp + OFF_T2;
    float* agg2   = sp + OFF_AGG2;
    float* t3     = sp + OFF_T3;
    float* agg3   = sp + OFF_AGG3;

    const int TB = 256;

    // 0) zero arena
    zero_kernel<<<(SCRATCH_TOTAL / 4 + TB - 1) / TB, TB>>>();
    // 1) degrees
    degree_kernel<<<(NE + TB - 1) / TB, TB>>>(src, dst);
    // 2) rsqrt norms
    rsqrt_kernel<<<(2 * NN + TB - 1) / TB, TB>>>();

    // Layer 1: t1 = (X @ W1) * rs_out ; agg1 = A t1
    gemm_kernel<128, 64, 0, 1><<<(NN + 15) / 16, TB>>>(
        features, W1, nullptr, nullptr, rs_out, nullptr, t1);
    spmm_kernel<64><<<(NE * 16 + TB - 1) / TB, TB>>>(src, dst, t1, agg1);

    // Layer 2: t2 = (relu(agg1*rs_in + b1) @ W2) * rs_out ; agg2 = A t2
    gemm_kernel<64, 32, 1, 1><<<(NN + 31) / 32, TB>>>(
        agg1, W2, rs_in, b1, rs_out, nullptr, t2);
    spmm_kernel<32><<<(NE * 8 + TB - 1) / TB, TB>>>(src, dst, t2, agg2);

    // z = agg2*rs_in + b2  (output) ; t3 = z * rs_out
    epilogue_kernel<<<(NN * 8 + TB - 1) / TB, TB>>>(b2, z_out);

    // Layer 3: agg3 = A t3 ; recon = (agg3*rs_in) @ W3 + b3
    spmm_kernel<32><<<(NE * 8 + TB - 1) / TB, TB>>>(src, dst, t3, agg3);
    gemm_kernel<32, 128, 2, 2><<<(NN + 7) / 8, TB>>>(
        agg3, W3, rs_in, nullptr, nullptr, b3, recon);
}

// round 3
// speedup vs baseline: 1.9053x; 1.9053x over previous
#include <cuda_runtime.h>

// Problem constants
#define NN 50000
#define NE 600000

// Scratch layout (floats). Region [0, ZERO_TOTAL) must be zeroed each replay.
#define OFF_RS_OUT 0
#define OFF_RS_IN  50000
#define OFF_AGG1   100000            // 50000*64
#define OFF_AGG2   3300000           // 50000*32
#define OFF_AGG3   4900000           // 50000*32
#define ZERO_TOTAL 6500000           // 26 MB zeroed
#define OFF_T1     6500000           // 50000*64
#define OFF_T2     9700000           // 50000*32
#define OFF_T3     11300000          // 50000*32
#define SCRATCH_TOTAL 12900000       // 51.6 MB

__device__ __align__(16) float g_scratch[SCRATCH_TOTAL];

// ---------------------------------------------------------------------------
// Zero only degrees + agg accumulators
// ---------------------------------------------------------------------------
__global__ void zero_kernel() {
    int i = blockIdx.x * blockDim.x + threadIdx.x;
    int n4 = ZERO_TOTAL / 4;
    if (i < n4) ((float4*)g_scratch)[i] = make_float4(0.f, 0.f, 0.f, 0.f);
}

// ---------------------------------------------------------------------------
// Degree histograms
// ---------------------------------------------------------------------------
__global__ void degree_kernel(const int* __restrict__ src, const int* __restrict__ dst) {
    int i = blockIdx.x * blockDim.x + threadIdx.x;
    if (i >= NE) return;
    atomicAdd(&g_scratch[OFF_RS_OUT + __ldg(&src[i])], 1.0f);
    atomicAdd(&g_scratch[OFF_RS_IN  + __ldg(&dst[i])], 1.0f);
}

__global__ void rsqrt_kernel() {
    int i = blockIdx.x * blockDim.x + threadIdx.x;
    if (i >= 2 * NN) return;
    g_scratch[i] = rsqrtf(fmaxf(g_scratch[i], 1.0f));
}

// ---------------------------------------------------------------------------
// Register-tiled GEMM with K-chunking (static smem <= 48KB, no attributes):
//   out[n, :J] = f_out( f_in(X[n, :K]) @ W )
//   Each thread: TN=4 nodes x 8 columns register tile.
//   K processed in KC-sized chunks; sW and sX re-staged per chunk.
//   MODE_IN : 0 raw, 1 relu(v*rs_in[n] + bin[k]), 2 v*rs_in[n]
//   MODE_OUT: 0 raw, 1 *rs_out[n],               2 +bout[j]
// ---------------------------------------------------------------------------
template<int K, int J, int KC, int MODE_IN, int MODE_OUT>
__global__ void __launch_bounds__(256) gemm_kernel(
    const float* __restrict__ X, const float* __restrict__ W,
    const float* __restrict__ rs_in, const float* __restrict__ bin,
    const float* __restrict__ rs_out, const float* __restrict__ bout,
    float* __restrict__ out)
{
    constexpr int TN = 4;                // nodes per thread
    constexpr int JV = J / 8;            // thread lanes across J (8 cols each)
    constexpr int NT = 256 / JV;         // thread rows
    constexpr int NB = NT * TN;          // nodes per block
    constexpr int XS = KC + 4;           // padded smem row stride

    __shared__ float sW[KC * J];
    __shared__ float sX[NB * XS];
    __shared__ float sRS[NB];

    const int nrow = threadIdx.x / JV;   // thread row (group of TN nodes)
    const int jv   = threadIdx.x % JV;   // column lane (cols 8*jv .. 8*jv+7)
    const int base = blockIdx.x * NB;

    if (MODE_OUT == 1 && threadIdx.x < NB) {
        int n = base + threadIdx.x;
        sRS[threadIdx.x] = (n < NN) ? __ldg(&rs_out[n]) : 0.f;
    }

    // Init accumulators (bias fused for MODE_OUT==2)
    float4 acc[TN][2];
    #pragma unroll
    for (int t = 0; t < TN; t++)
        #pragma unroll
        for (int c = 0; c < 2; c++) {
            if (MODE_OUT == 2) acc[t][c] = __ldg((const float4*)&bout[8 * jv + 4 * c]);
            else               acc[t][c] = make_float4(0.f, 0.f, 0.f, 0.f);
        }

    const float* xs = &sX[(nrow * TN) * XS];

    #pragma unroll 1
    for (int k0 = 0; k0 < K; k0 += KC) {
        __syncthreads();
        // Stage W chunk (rows k0..k0+KC of row-major [K,J])
        for (int i = threadIdx.x; i < KC * J / 4; i += 256)
            ((float4*)sW)[i] = __ldg(&((const float4*)(W + (size_t)k0 * J))[i]);
        // Stage X chunk with fused input transform
        for (int i = threadIdx.x; i < NB * (KC / 4); i += 256) {
            int nl = i / (KC / 4);
            int kc = i % (KC / 4);
            int n = base + nl;
            float4 v = make_float4(0.f, 0.f, 0.f, 0.f);
            if (n < NN) {
                v = __ldg((const float4*)&X[(size_t)n * K + k0 + 4 * kc]);
                if (MODE_IN == 1) {
                    float r = __ldg(&rs_in[n]);
                    float4 b = __ldg((const float4*)&bin[k0 + 4 * kc]);
                    v.x = fmaxf(fmaf(v.x, r, b.x), 0.f);
                    v.y = fmaxf(fmaf(v.y, r, b.y), 0.f);
                    v.z = fmaxf(fmaf(v.z, r, b.z), 0.f);
                    v.w = fmaxf(fmaf(v.w, r, b.w), 0.f);
                } else if (MODE_IN == 2) {
                    float r = __ldg(&rs_in[n]);
                    v.x *= r; v.y *= r; v.z *= r; v.w *= r;
                }
            }
            *(float4*)&sX[nl * XS + 4 * kc] = v;
        }
        __syncthreads();

        #pragma unroll 8
        for (int k = 0; k < KC; k++) {
            float4 w0 = *(const float4*)&sW[k * J + 8 * jv];
            float4 w1 = *(const float4*)&sW[k * J + 8 * jv + 4];
            #pragma unroll
            for (int t = 0; t < TN; t++) {
                float xk = xs[t * XS + k];
                acc[t][0].x = fmaf(xk, w0.x, acc[t][0].x);
                acc[t][0].y = fmaf(xk, w0.y, acc[t][0].y);
                acc[t][0].z = fmaf(xk, w0.z, acc[t][0].z);
                acc[t][0].w = fmaf(xk, w0.w, acc[t][0].w);
                acc[t][1].x = fmaf(xk, w1.x, acc[t][1].x);
                acc[t][1].y = fmaf(xk, w1.y, acc[t][1].y);
                acc[t][1].z = fmaf(xk, w1.z, acc[t][1].z);
                acc[t][1].w = fmaf(xk, w1.w, acc[t][1].w);
            }
        }
    }

    // Store
    #pragma unroll
    for (int t = 0; t < TN; t++) {
        int nl = nrow * TN + t;
        int n = base + nl;
        if (n < NN) {
            if (MODE_OUT == 1) {
                float r = sRS[nl];
                #pragma unroll
                for (int c = 0; c < 2; c++) {
                    acc[t][c].x *= r; acc[t][c].y *= r;
                    acc[t][c].z *= r; acc[t][c].w *= r;
                }
            }
            *(float4*)&out[(size_t)n * J + 8 * jv]     = acc[t][0];
            *(float4*)&out[(size_t)n * J + 8 * jv + 4] = acc[t][1];
        }
    }
}

// ---------------------------------------------------------------------------
// SpMM scatter-add with red.global.add.v4.f32
// ---------------------------------------------------------------------------
template<int F>
__global__ void spmm_kernel(const int* __restrict__ src, const int* __restrict__ dst,
                            const float* __restrict__ tin, float* __restrict__ agg)
{
    constexpr int C = F / 4;
    int i = blockIdx.x * blockDim.x + threadIdx.x;
    if (i >= NE * C) return;
    int e = i / C;
    int c = i % C;
    int s = __ldg(&src[e]);
    int d = __ldg(&dst[e]);
    float4 v = __ldg((const float4*)(tin + (size_t)s * F + 4 * c));
    float* p = agg + (size_t)d * F + 4 * c;
    asm volatile("red.global.add.v4.f32 [%0], {%1, %2, %3, %4};"
                 :: "l"(p), "f"(v.x), "f"(v.y), "f"(v.z), "f"(v.w)
                 : "memory");
}

// ---------------------------------------------------------------------------
// Layer-2 epilogue: z = agg2*rs_in + b2 (to output); t3 = z * rs_out
// ---------------------------------------------------------------------------
__global__ void epilogue_kernel(const float* __restrict__ b2, float* __restrict__ z_out) {
    int i = blockIdx.x * blockDim.x + threadIdx.x;
    if (i >= NN * 8) return;
    int n = i >> 3;
    int kc = i & 7;
    float rin  = g_scratch[OFF_RS_IN + n];
    float rout = g_scratch[OFF_RS_OUT + n];
    float4 a = *(const float4*)&g_scratch[OFF_AGG2 + (size_t)n * 32 + 4 * kc];
    float4 b = __ldg((const float4*)&b2[4 * kc]);
    float4 z;
    z.x = fmaf(a.x, rin, b.x);
    z.y = fmaf(a.y, rin, b.y);
    z.z = fmaf(a.z, rin, b.z);
    z.w = fmaf(a.w, rin, b.w);
    *(float4*)&z_out[(size_t)n * 32 + 4 * kc] = z;
    float4 t;
    t.x = z.x * rout; t.y = z.y * rout; t.z = z.z * rout; t.w = z.w * rout;
    *(float4*)&g_scratch[OFF_T3 + (size_t)n * 32 + 4 * kc] = t;
}

// ---------------------------------------------------------------------------
extern "C" void kernel_launch(void* const* d_in, const int* in_sizes, int n_in,
                              void* d_out, int out_size)
{
    const float* features = (const float*)d_in[0];
    const int*   src      = (const int*)d_in[1];
    const int*   dst      = (const int*)d_in[2];
    const float* W1       = (const float*)d_in[3];
    const float* b1       = (const float*)d_in[4];
    const float* W2       = (const float*)d_in[5];
    const float* b2       = (const float*)d_in[6];
    const float* W3       = (const float*)d_in[7];
    const float* b3       = (const float*)d_in[8];

    float* z_out = (float*)d_out;                    // [50000, 32]
    float* recon = (float*)d_out + (size_t)NN * 32;  // [50000, 128]

    float* sp = nullptr;
    cudaGetSymbolAddress((void**)&sp, g_scratch);
    float* rs_out = sp + OFF_RS_OUT;
    float* rs_in  = sp + OFF_RS_IN;
    float* agg1   = sp + OFF_AGG1;
    float* agg2   = sp + OFF_AGG2;
    float* agg3   = sp + OFF_AGG3;
    float* t1     = sp + OFF_T1;
    float* t2     = sp + OFF_T2;
    float* t3     = sp + OFF_T3;

    const int TB = 256;

    // 0) zero degrees + agg buffers
    zero_kernel<<<(ZERO_TOTAL / 4 + TB - 1) / TB, TB>>>();
    // 1) degrees
    degree_kernel<<<(NE + TB - 1) / TB, TB>>>(src, dst);
    // 2) rsqrt norms
    rsqrt_kernel<<<(2 * NN + TB - 1) / TB, TB>>>();

    // Layer 1: t1 = (X @ W1) * rs_out ; agg1 = A t1       (NB=128, KC=32)
    gemm_kernel<128, 64, 32, 0, 1><<<(NN + 127) / 128, TB>>>(
        features, W1, nullptr, nullptr, rs_out, nullptr, t1);
    spmm_kernel<64><<<(NE * 16 + TB - 1) / TB, TB>>>(src, dst, t1, agg1);

    // Layer 2: t2 = (relu(agg1*rs_in + b1) @ W2) * rs_out ; agg2 = A t2  (NB=256, KC=32)
    gemm_kernel<64, 32, 32, 1, 1><<<(NN + 255) / 256, TB>>>(
        agg1, W2, rs_in, b1, rs_out, nullptr, t2);
    spmm_kernel<32><<<(NE * 8 + TB - 1) / TB, TB>>>(src, dst, t2, agg2);

    // z = agg2*rs_in + b2 (output) ; t3 = z * rs_out
    epilogue_kernel<<<(NN * 8 + TB - 1) / TB, TB>>>(b2, z_out);

    // Layer 3: agg3 = A t3 ; recon = (agg3*rs_in) @ W3 + b3   (NB=64, KC=32)
    spmm_kernel<32><<<(NE * 8 + TB - 1) / TB, TB>>>(src, dst, t3, agg3);
    gemm_kernel<32, 128, 32, 2, 2><<<(NN + 63) / 64, TB>>>(
        agg3, W3, rs_in, nullptr, nullptr, b3, recon);
}